// round 13
// baseline (speedup 1.0000x reference)
#include <cuda_runtime.h>
#include <cstdint>
#include <cstddef>

// LowRankINRLayer: out = relu( (x @ v^T) @ W^T )
//   x [16,8192,512] f32, v [16,32,512] f32, W [512,32] f32 -> out f32
//
// Round 13: persistent version of R12. 256 CTAs x 4 tiles; the 3-stage
// cp.async pipeline runs as one flat 64-chunk stream across the CTA's tiles,
// so the next tile's loads are in flight during the current tile's epilogue
// and there is no wave-quantization tail. Mainloop/epilogue bodies = R12
// (ldmatrix fragments, tf32 mma.sync, staged STG.128, prep-blocked tf32 v).

namespace {

constexpr int kB  = 16;
constexpr int kN  = 8192;
constexpr int kDI = 512;
constexpr int kDO = 512;
constexpr int kR  = 32;

constexpr int TM      = 128;          // rows per tile
constexpr int KC      = 32;           // K per pipeline chunk
constexpr int NCH     = kDI / KC;     // 16 chunks per tile
constexpr int NTILES  = 4;            // tiles per CTA
constexpr int NGC     = NTILES * NCH; // 64 flat chunks per CTA
constexpr int STAGES  = 3;
constexpr int THREADS = 256;          // 8 warps
constexpr int GRID    = (kB * (kN / TM)) / NTILES;   // 256

constexpr int XW = KC + 4;                          // 36 words row stride (144B)
constexpr int XBUF = TM * XW;                       // 4608 words / stage
constexpr int VBUF = kR * XW;                       // 1152 words / stage
constexpr int V_OFF = STAGES * XBUF;                // 13824
constexpr int STG_OFF = V_OFF + STAGES * VBUF;      // 17280 (staging region)
constexpr int STG_PER_WARP = 16 * 64;               // 1024 words (4 KB)
constexpr int SMEM_WORDS = STG_OFF + 8 * STG_PER_WARP;   // 25472
constexpr int SMEM_BYTES = SMEM_WORDS * 4;               // 101888 B -> 2 CTAs/SM

// tf32(RNA) scratch, filled by prep kernel
__device__ unsigned g_v[kB * kR * kDI];   // blocked [b][ck][n][kk], kk<32

__device__ __forceinline__ unsigned f2tf(float f) {
    unsigned u;
    asm("cvt.rna.tf32.f32 %0, %1;" : "=r"(u) : "f"(f));
    return u;
}
__device__ __forceinline__ unsigned f2tf_u(unsigned raw) {
    return f2tf(__uint_as_float(raw));
}

__device__ __forceinline__ void ldsm4(unsigned& r0, unsigned& r1,
                                      unsigned& r2, unsigned& r3, unsigned a) {
    asm volatile("ldmatrix.sync.aligned.m8n8.x4.shared.b16 {%0,%1,%2,%3}, [%4];"
                 : "=r"(r0), "=r"(r1), "=r"(r2), "=r"(r3) : "r"(a));
}

__device__ __forceinline__ void mma_tf32(float& d0, float& d1, float& d2, float& d3,
                                         unsigned a0, unsigned a1, unsigned a2, unsigned a3,
                                         unsigned b0, unsigned b1) {
    asm volatile(
        "mma.sync.aligned.m16n8k8.row.col.f32.tf32.tf32.f32 "
        "{%0,%1,%2,%3}, {%4,%5,%6,%7}, {%8,%9}, {%0,%1,%2,%3};"
        : "+f"(d0), "+f"(d1), "+f"(d2), "+f"(d3)
        : "r"(a0), "r"(a1), "r"(a2), "r"(a3), "r"(b0), "r"(b1));
}

__device__ __forceinline__ void cp16(unsigned dst_smem, const void* src) {
    asm volatile("cp.async.cg.shared.global [%0], [%1], 16;"
                 :: "r"(dst_smem), "l"(src) : "memory");
}

// ---- prep: v -> tf32 RNA blocked [b][ck][n][kk] (262144 elements) ----
__global__ void prep_kernel(const float* __restrict__ v) {
    int idx = blockIdx.x * 256 + threadIdx.x;   // grid 1024
    int b = idx >> 14, rem = idx & 16383;
    int n = rem >> 9, k = rem & 511;
    int ck = k >> 5, kk = k & 31;
    g_v[(b << 14) + (ck << 10) + (n << 5) + kk] = f2tf(v[idx]);
}

__global__ void __launch_bounds__(THREADS, 2)
lowrank_kernel(const float* __restrict__ x,
               const float* __restrict__ W,
               float* __restrict__ out)
{
    extern __shared__ unsigned smu[];
    const unsigned sbase = (unsigned)__cvta_generic_to_shared(smu);

    const int tid  = threadIdx.x;
    const int lane = tid & 31;
    const int warp = tid >> 5;
    const int g    = lane >> 2;
    const int t4   = lane & 3;
    const int mw   = warp * 16;
    const int bid4 = blockIdx.x * NTILES;

    // flat-chunk issue: gi in [0,64) -> tile bid4 + (gi>>4), chunk gi&15
    auto issue = [&](int gi, int si) {
        const int tl = bid4 + (gi >> 4);
        const int cc = gi & 15;
        const int b2 = tl >> 6;
        const int m2 = (tl & 63) << 7;
        const float*    xg = x + ((size_t)b2 * kN + m2) * kDI + cc * KC;
        const unsigned* gv = g_v + (size_t)b2 * (kR * kDI) + cc * (kR * KC);
        const unsigned xd = sbase + (unsigned)(si * XBUF) * 4u;
        #pragma unroll
        for (int i = 0; i < 4; i++) {
            const int q = tid + 256 * i;     // 1024 x 16B units
            const int r = q >> 3, u = q & 7;
            cp16(xd + (unsigned)(r * XW + u * 4) * 4u,
                 xg + (size_t)r * kDI + u * 4);
        }
        const int vr = tid >> 3, vu = tid & 7;
        const unsigned vd = sbase + (unsigned)(V_OFF + si * VBUF) * 4u;
        cp16(vd + (unsigned)(vr * XW + vu * 4) * 4u, gv + vr * KC + vu * 4);
        asm volatile("cp.async.commit_group;" ::: "memory");
    };

    issue(0, 0);
    issue(1, 1);

    // ldmatrix per-lane address components (byte offsets within a stage)
    const unsigned a_boff = (unsigned)(mw + (lane & 15)) * 144u
                          + (unsigned)((lane >> 4) * 16);
    const unsigned b_boff = (unsigned)(((lane >> 4) << 3) + (lane & 7)) * 144u
                          + (unsigned)(((lane >> 3) & 1) * 16);

    float acc[4][4] = {};
    int s = 0;                                 // stage of current chunk

    #pragma unroll 1
    for (int tt = 0; tt < NTILES; tt++) {
        const int tile = bid4 + tt;
        const int tb = tile >> 6;
        const int tm0 = (tile & 63) << 7;

        #pragma unroll 1
        for (int c = 0; c < NCH; c++) {
            const int gc = tt * NCH + c;
            if (gc < NGC - 1) asm volatile("cp.async.wait_group 1;" ::: "memory");
            else              asm volatile("cp.async.wait_group 0;" ::: "memory");
            __syncthreads();   // chunk gc ready; prior stage fully consumed

            if (gc + 2 < NGC) {
                int si = s + 2; if (si >= STAGES) si -= STAGES;
                issue(gc + 2, si);             // overwrites stage (gc-1)%3
            }

            const unsigned xa = sbase + (unsigned)(s * XBUF) * 4u + a_boff;
            const unsigned vb = sbase + (unsigned)(V_OFF + s * VBUF) * 4u + b_boff;

            #pragma unroll
            for (int ks = 0; ks < 4; ks++) {
                unsigned ra0, ra1, ra2, ra3;
                ldsm4(ra0, ra1, ra2, ra3, xa + 32u * ks);
                unsigned a0 = f2tf_u(ra0), a1 = f2tf_u(ra1);
                unsigned a2 = f2tf_u(ra2), a3 = f2tf_u(ra3);
                #pragma unroll
                for (int nbp = 0; nbp < 2; nbp++) {
                    unsigned b00, b01, b10, b11;
                    ldsm4(b00, b01, b10, b11, vb + (unsigned)(nbp * 2304) + 32u * ks);
                    mma_tf32(acc[2*nbp][0],   acc[2*nbp][1],   acc[2*nbp][2],   acc[2*nbp][3],
                             a0, a1, a2, a3, b00, b01);
                    mma_tf32(acc[2*nbp+1][0], acc[2*nbp+1][1], acc[2*nbp+1][2], acc[2*nbp+1][3],
                             a0, a1, a2, a3, b10, b11);
                }
            }
            if (++s == STAGES) s = 0;
        }

        // ---- epilogue for tile tt; C1 reuses the just-consumed stage ----
        // stage of chunk (16*tt+15) = (16*tt+15)%3 = tt%3
        const int sc1 = (tt == 3) ? 0 : tt;
        __syncthreads();   // all warps done reading stage sc1 (chunk 16tt+15)

        float* c1 = (float*)smu + sc1 * XBUF;
        #pragma unroll
        for (int nb = 0; nb < 4; nb++) {
            *reinterpret_cast<float2*>(&c1[(mw + g)     * XW + nb * 8 + 2 * t4]) =
                make_float2(acc[nb][0], acc[nb][1]);
            *reinterpret_cast<float2*>(&c1[(mw + g + 8) * XW + nb * 8 + 2 * t4]) =
                make_float2(acc[nb][2], acc[nb][3]);
        }
        __syncthreads();

        #pragma unroll
        for (int nb = 0; nb < 4; nb++)
            #pragma unroll
            for (int q = 0; q < 4; q++) acc[nb][q] = 0.f;

        // W fragments for warp's o-cols [warp*64, warp*64+64) (L2-hot reload)
        const int oc0 = warp * 64;
        unsigned wf[8][4][2];
        #pragma unroll
        for (int ob = 0; ob < 8; ob++) {
            const float* wr = W + (size_t)(oc0 + ob * 8 + g) * kR;
            #pragma unroll
            for (int ks = 0; ks < 4; ks++) {
                wf[ob][ks][0] = f2tf(wr[ks * 8 + t4]);
                wf[ob][ks][1] = f2tf(wr[ks * 8 + t4 + 4]);
            }
        }

        float* stg = (float*)smu + STG_OFF + warp * STG_PER_WARP;
        float* ob_ = out + ((size_t)tb * kN + tm0) * kDO;

        #pragma unroll 1
        for (int mb = 0; mb < TM / 16; mb++) {
            const unsigned ca = sbase + (unsigned)(sc1 * XBUF) * 4u
                              + (unsigned)(mb * 16 + (lane & 15)) * 144u
                              + (unsigned)((lane >> 4) * 16);
            unsigned a[4][4];
            #pragma unroll
            for (int ks = 0; ks < 4; ks++) {
                unsigned r0, r1, r2, r3;
                ldsm4(r0, r1, r2, r3, ca + 32u * ks);
                a[ks][0] = f2tf_u(r0); a[ks][1] = f2tf_u(r1);
                a[ks][2] = f2tf_u(r2); a[ks][3] = f2tf_u(r3);
            }
            const int sw = (g & 3) << 3;
            #pragma unroll
            for (int ob = 0; ob < 8; ob++) {
                float d0 = 0.f, d1 = 0.f, d2 = 0.f, d3 = 0.f;
                #pragma unroll
                for (int ks = 0; ks < 4; ks++)
                    mma_tf32(d0, d1, d2, d3,
                             a[ks][0], a[ks][1], a[ks][2], a[ks][3],
                             wf[ob][ks][0], wf[ob][ks][1]);
                const int lc = (ob * 8 + 2 * t4) ^ sw;
                *reinterpret_cast<float2*>(&stg[g * 64 + lc]) =
                    make_float2(fmaxf(d0, 0.f), fmaxf(d1, 0.f));
                *reinterpret_cast<float2*>(&stg[(g + 8) * 64 + lc]) =
                    make_float2(fmaxf(d2, 0.f), fmaxf(d3, 0.f));
            }
            __syncwarp();
            const int half = lane >> 4;
            const int colw = (lane & 15) * 4;
            #pragma unroll
            for (int i = 0; i < 8; i++) {
                const int row = 2 * i + half;
                const int sc  = colw ^ ((row & 3) << 3);
                float4 val = *reinterpret_cast<float4*>(&stg[row * 64 + sc]);
                *reinterpret_cast<float4*>(
                    &ob_[(size_t)(mb * 16 + row) * kDO + oc0 + colw]) = val;
            }
            __syncwarp();
        }
        // next iteration's top __syncthreads guards stage sc1 reuse
    }
}

} // namespace

extern "C" void kernel_launch(void* const* d_in, const int* in_sizes, int n_in,
                              void* d_out, int out_size) {
    (void)in_sizes; (void)n_in; (void)out_size;
    const float* x = (const float*)d_in[0];
    const float* v = (const float*)d_in[1];
    const float* W = (const float*)d_in[2];
    float* out = (float*)d_out;

    prep_kernel<<<1024, 256>>>(v);

    cudaFuncSetAttribute(lowrank_kernel,
                         cudaFuncAttributeMaxDynamicSharedMemorySize, SMEM_BYTES);
    lowrank_kernel<<<GRID, THREADS, SMEM_BYTES>>>(x, W, out);
}

// round 14
// speedup vs baseline: 1.0865x; 1.0865x over previous
#include <cuda_runtime.h>
#include <cstdint>
#include <cstddef>

// LowRankINRLayer: out = relu( (x @ v^T) @ W^T )
//   x [16,8192,512] f32, v [16,32,512] f32, W [512,32] f32 -> out f32
//
// Round 14: R12 main kernel verbatim (tf32 mma.sync, 4-stage cp.async KC=32,
// TM=128, 256 thr, 92KB smem, 2 CTAs/SM, ldmatrix fragment loads, prep-blocked
// tf32 v, W register-resident, staged STG.128 epilogue) + vectorized prep
// (float4 in/out, 2-deep MLP, 128 blocks) cutting prep from ~4.9us to ~2us.

namespace {

constexpr int kB  = 16;
constexpr int kN  = 8192;
constexpr int kDI = 512;
constexpr int kDO = 512;
constexpr int kR  = 32;

constexpr int TM      = 128;          // rows per CTA
constexpr int KC      = 32;           // K per pipeline chunk
constexpr int NCH     = kDI / KC;     // 16
constexpr int STAGES  = 4;
constexpr int THREADS = 256;          // 8 warps

constexpr int XW = KC + 4;                          // 36 words row stride (144 B)
constexpr int XBUF = TM * XW;                       // 4608 words / stage
constexpr int VBUF = kR * XW;                       // 1152 words / stage
constexpr int V_OFF = STAGES * XBUF;                // 18432
constexpr int SMEM_WORDS = V_OFF + STAGES * VBUF;   // 23040
constexpr int SMEM_BYTES = SMEM_WORDS * 4;          // 92160 B -> 2 CTAs/SM

// epilogue staging: warp-private 16 rows x 64 words, inside stage-1..3 region
constexpr int STG_OFF = XBUF;                       // word 4608 (stage 1 start)
constexpr int STG_PER_WARP = 16 * 64;               // 1024 words (4 KB)

// tf32(RNA) scratch, filled by prep kernel
__device__ unsigned g_v[kB * kR * kDI];   // blocked [b][ck][n][kk], kk<32

__device__ __forceinline__ unsigned f2tf(float f) {
    unsigned u;
    asm("cvt.rna.tf32.f32 %0, %1;" : "=r"(u) : "f"(f));
    return u;
}
__device__ __forceinline__ unsigned f2tf_u(unsigned raw) {
    return f2tf(__uint_as_float(raw));
}

__device__ __forceinline__ void ldsm4(unsigned& r0, unsigned& r1,
                                      unsigned& r2, unsigned& r3, unsigned a) {
    asm volatile("ldmatrix.sync.aligned.m8n8.x4.shared.b16 {%0,%1,%2,%3}, [%4];"
                 : "=r"(r0), "=r"(r1), "=r"(r2), "=r"(r3) : "r"(a));
}

__device__ __forceinline__ void mma_tf32(float& d0, float& d1, float& d2, float& d3,
                                         unsigned a0, unsigned a1, unsigned a2, unsigned a3,
                                         unsigned b0, unsigned b1) {
    asm volatile(
        "mma.sync.aligned.m16n8k8.row.col.f32.tf32.tf32.f32 "
        "{%0,%1,%2,%3}, {%4,%5,%6,%7}, {%8,%9}, {%0,%1,%2,%3};"
        : "+f"(d0), "+f"(d1), "+f"(d2), "+f"(d3)
        : "r"(a0), "r"(a1), "r"(a2), "r"(a3), "r"(b0), "r"(b1));
}

__device__ __forceinline__ void cp16(unsigned dst_smem, const void* src) {
    asm volatile("cp.async.cg.shared.global [%0], [%1], 16;"
                 :: "r"(dst_smem), "l"(src) : "memory");
}

// ---- prep: v -> tf32 RNA blocked [b][ck][n][kk], vectorized float4 ----
// 65536 float4s total; 128 blocks x 256 threads x 2 float4s (MLP 2).
// k%4==0 within a 32-block => output kk%4==0, same ck: float4-contiguous.
__global__ void __launch_bounds__(256, 4) prep_kernel(const float* __restrict__ v) {
    const int base = blockIdx.x * 256 + threadIdx.x;
    float4 in0 = *reinterpret_cast<const float4*>(v + 4 * (size_t)base);
    float4 in1 = *reinterpret_cast<const float4*>(v + 4 * (size_t)(base + 32768));
    #pragma unroll
    for (int i = 0; i < 2; i++) {
        const int f4 = base + i * 32768;
        const int e  = f4 * 4;
        const int b  = e >> 14, rem = e & 16383;
        const int n  = rem >> 9, k = rem & 511;
        const int ck = k >> 5, kk = k & 31;
        const float4 in = i ? in1 : in0;
        uint4 o = make_uint4(f2tf(in.x), f2tf(in.y), f2tf(in.z), f2tf(in.w));
        *reinterpret_cast<uint4*>(&g_v[(b << 14) + (ck << 10) + (n << 5) + kk]) = o;
    }
}

__global__ void __launch_bounds__(THREADS, 2)
lowrank_kernel(const float* __restrict__ x,
               const float* __restrict__ W,
               float* __restrict__ out)
{
    extern __shared__ unsigned smu[];
    const unsigned sbase = (unsigned)__cvta_generic_to_shared(smu);

    const int tid  = threadIdx.x;
    const int lane = tid & 31;
    const int warp = tid >> 5;
    const int g    = lane >> 2;
    const int t4   = lane & 3;
    const int mw   = warp * 16;

    const int b  = blockIdx.x >> 6;          // 64 tiles per batch
    const int m0 = (blockIdx.x & 63) * TM;

    const float*    xg  = x + ((size_t)b * kN + m0) * kDI;
    const unsigned* gvb = g_v + (size_t)b * (kR * kDI);

    const int vr = tid >> 3, vu = tid & 7;   // v: 256 x 16B units, 1/thread

    auto issue = [&](int c) {
        const int s = c & (STAGES - 1);
        const unsigned xd = sbase + (unsigned)(s * XBUF) * 4u;
        #pragma unroll
        for (int i = 0; i < 4; i++) {
            const int q = tid + 256 * i;     // 1024 x 16B units
            const int r = q >> 3, u = q & 7;
            cp16(xd + (unsigned)(r * XW + u * 4) * 4u,
                 xg + (size_t)r * kDI + c * KC + u * 4);
        }
        const unsigned vd = sbase + (unsigned)(V_OFF + s * VBUF) * 4u;
        cp16(vd + (unsigned)(vr * XW + vu * 4) * 4u,
             gvb + c * (kR * KC) + vr * KC + vu * 4);
        asm volatile("cp.async.commit_group;" ::: "memory");
    };

    issue(0); issue(1); issue(2);

    // ldmatrix per-lane address components (byte offsets within a stage)
    //   a-frag m16k8: lanes 0-15 -> rows mw+0..15 (+0B), lanes 16-31 -> +16B
    const unsigned a_boff = (unsigned)(mw + (lane & 15)) * 144u
                          + (unsigned)((lane >> 4) * 16);
    //   b-frag k8n8 pair: grp0/1 rows nbp*16+(lane&7) at +0/+16B, grp2/3 rows +8
    const unsigned b_boff = (unsigned)(((lane >> 4) << 3) + (lane & 7)) * 144u
                          + (unsigned)(((lane >> 3) & 1) * 16);

    // ---- GEMM1 mainloop: acc = x_tile @ v^T (per warp: m=16, n=32) ----
    float acc[4][4] = {};

    for (int c = 0; c < NCH; ++c) {
        if (c < NCH - 2)        asm volatile("cp.async.wait_group 2;" ::: "memory");
        else if (c == NCH - 2)  asm volatile("cp.async.wait_group 1;" ::: "memory");
        else                    asm volatile("cp.async.wait_group 0;" ::: "memory");
        __syncthreads();   // chunk c ready; chunk c-1 consumed by all warps

        if (c + 3 < NCH) issue(c + 3);   // writes stage (c-1)&3, now free

        const unsigned xa = sbase + (unsigned)((c & 3) * XBUF) * 4u + a_boff;
        const unsigned vb = sbase + (unsigned)((V_OFF + (c & 3) * VBUF)) * 4u + b_boff;

        #pragma unroll
        for (int ks = 0; ks < 4; ks++) {
            unsigned ra0, ra1, ra2, ra3;
            ldsm4(ra0, ra1, ra2, ra3, xa + 32u * ks);
            unsigned a0 = f2tf_u(ra0), a1 = f2tf_u(ra1);
            unsigned a2 = f2tf_u(ra2), a3 = f2tf_u(ra3);
            #pragma unroll
            for (int nbp = 0; nbp < 2; nbp++) {
                unsigned b00, b01, b10, b11;   // (b0,b1) for nb=2nbp, 2nbp+1
                ldsm4(b00, b01, b10, b11, vb + (unsigned)(nbp * 2304) + 32u * ks);
                mma_tf32(acc[2*nbp][0],   acc[2*nbp][1],   acc[2*nbp][2],   acc[2*nbp][3],
                         a0, a1, a2, a3, b00, b01);
                mma_tf32(acc[2*nbp+1][0], acc[2*nbp+1][1], acc[2*nbp+1][2], acc[2*nbp+1][3],
                         a0, a1, a2, a3, b10, b11);
            }
        }
    }

    // ---- C1 (128x32 f32) -> smem (stage-0 region), stride 36 words ----
    __syncthreads();
    float* c1 = (float*)smu;
    #pragma unroll
    for (int nb = 0; nb < 4; nb++) {
        *reinterpret_cast<float2*>(&c1[(mw + g)     * XW + nb * 8 + 2 * t4]) =
            make_float2(acc[nb][0], acc[nb][1]);
        *reinterpret_cast<float2*>(&c1[(mw + g + 8) * XW + nb * 8 + 2 * t4]) =
            make_float2(acc[nb][2], acc[nb][3]);
    }
    __syncthreads();

    // ---- GEMM2: relu(C1 @ W^T); warp owns o-cols [warp*64, warp*64+64) ----
    const int oc0 = warp * 64;
    unsigned wf[8][4][2];
    #pragma unroll
    for (int ob = 0; ob < 8; ob++) {
        const float* wr = W + (size_t)(oc0 + ob * 8 + g) * kR;
        #pragma unroll
        for (int ks = 0; ks < 4; ks++) {
            wf[ob][ks][0] = f2tf(wr[ks * 8 + t4]);
            wf[ob][ks][1] = f2tf(wr[ks * 8 + t4 + 4]);
        }
    }

    // warp-private staging buffer: 16 rows x 64 words, XOR-8 swizzled
    float* stg = (float*)smu + STG_OFF + warp * STG_PER_WARP;
    float* ob_ = out + ((size_t)b * kN + m0) * kDO;

    #pragma unroll 1
    for (int mb = 0; mb < TM / 16; mb++) {
        // a-frags from C1 via ldmatrix (rows mb*16 + lane%16, stride 144B)
        const unsigned ca = sbase + (unsigned)(mb * 16 + (lane & 15)) * 144u
                                  + (unsigned)((lane >> 4) * 16);
        unsigned a[4][4];
        #pragma unroll
        for (int ks = 0; ks < 4; ks++) {
            unsigned r0, r1, r2, r3;
            ldsm4(r0, r1, r2, r3, ca + 32u * ks);
            a[ks][0] = f2tf_u(r0); a[ks][1] = f2tf_u(r1);
            a[ks][2] = f2tf_u(r2); a[ks][3] = f2tf_u(r3);
        }
        // compute + stage (STS.64, conflict-free under XOR-8 swizzle)
        const int sw = (g & 3) << 3;                 // same for row g and g+8
        #pragma unroll
        for (int ob = 0; ob < 8; ob++) {
            float d0 = 0.f, d1 = 0.f, d2 = 0.f, d3 = 0.f;
            #pragma unroll
            for (int ks = 0; ks < 4; ks++)
                mma_tf32(d0, d1, d2, d3,
                         a[ks][0], a[ks][1], a[ks][2], a[ks][3],
                         wf[ob][ks][0], wf[ob][ks][1]);
            const int lc = (ob * 8 + 2 * t4) ^ sw;   // XOR keeps 2-word alignment
            *reinterpret_cast<float2*>(&stg[g * 64 + lc]) =
                make_float2(fmaxf(d0, 0.f), fmaxf(d1, 0.f));
            *reinterpret_cast<float2*>(&stg[(g + 8) * 64 + lc]) =
                make_float2(fmaxf(d2, 0.f), fmaxf(d3, 0.f));
        }
        __syncwarp();
        // readback (LDS.128, conflict-free) + full-line STG.128
        const int half = lane >> 4;                  // 0/1
        const int colw = (lane & 15) * 4;            // 0..60
        #pragma unroll
        for (int i = 0; i < 8; i++) {
            const int row = 2 * i + half;
            const int sc  = colw ^ ((row & 3) << 3);
            float4 val = *reinterpret_cast<float4*>(&stg[row * 64 + sc]);
            *reinterpret_cast<float4*>(
                &ob_[(size_t)(mb * 16 + row) * kDO + oc0 + colw]) = val;
        }
        __syncwarp();   // staging reused next mb
    }
}

} // namespace

extern "C" void kernel_launch(void* const* d_in, const int* in_sizes, int n_in,
                              void* d_out, int out_size) {
    (void)in_sizes; (void)n_in; (void)out_size;
    const float* x = (const float*)d_in[0];
    const float* v = (const float*)d_in[1];
    const float* W = (const float*)d_in[2];
    float* out = (float*)d_out;

    prep_kernel<<<128, 256>>>(v);

    cudaFuncSetAttribute(lowrank_kernel,
                         cudaFuncAttributeMaxDynamicSharedMemorySize, SMEM_BYTES);
    lowrank_kernel<<<kB * (kN / TM), THREADS, SMEM_BYTES>>>(x, W, out);
}